// round 1
// baseline (speedup 1.0000x reference)
#include <cuda_runtime.h>
#include <cuda_bf16.h>

// out[b,t,c] = (x[b,src,c] + noise[b,src,c]*0.1f) * scale[b]
// src = (t - (shifts[b] - MAX_SHIFT)) mod T
// B=64, T=4096, C=128, fp32. Pure HBM-streaming problem.

#define B_DIM 64
#define T_DIM 4096
#define C_DIM 128
#define MAX_SHIFT 409
#define NOISE_STD 0.1f

// C/4 = 32 float4 per (b,t) row
#define C4 (C_DIM / 4)

__global__ __launch_bounds__(256)
void ts_augment_kernel(const float4* __restrict__ x,
                       const float4* __restrict__ noise,
                       const float*  __restrict__ scale,
                       const int*    __restrict__ shifts,
                       float4*       __restrict__ out)
{
    // flat index over B * T * C4
    unsigned idx = blockIdx.x * blockDim.x + threadIdx.x;
    // total = 64 * 4096 * 32 = 8388608, exactly grid*block; no bounds check needed
    unsigned c4 = idx & (C4 - 1);          // idx % 32
    unsigned t  = (idx >> 5) & (T_DIM - 1); // (idx / 32) % 4096
    unsigned b  = idx >> 17;                // idx / (32*4096)

    int s = shifts[b] - MAX_SHIFT;          // [-409, 409]
    int src = (int)t - s;                   // [-409, 4504]
    if (src < 0)        src += T_DIM;
    else if (src >= T_DIM) src -= T_DIM;

    unsigned src_idx = (b << 17) + ((unsigned)src << 5) + c4;

    float4 xv = __ldg(&x[src_idx]);
    float4 nv = __ldg(&noise[src_idx]);
    float sc = __ldg(&scale[b]);

    float4 o;
    o.x = fmaf(nv.x, NOISE_STD, xv.x) * sc;
    o.y = fmaf(nv.y, NOISE_STD, xv.y) * sc;
    o.z = fmaf(nv.z, NOISE_STD, xv.z) * sc;
    o.w = fmaf(nv.w, NOISE_STD, xv.w) * sc;

    out[idx] = o;
}

extern "C" void kernel_launch(void* const* d_in, const int* in_sizes, int n_in,
                              void* d_out, int out_size)
{
    const float4* x      = (const float4*)d_in[0];
    const float4* noise  = (const float4*)d_in[1];
    const float*  scale  = (const float*)d_in[2];
    const int*    shifts = (const int*)d_in[3];
    float4* out = (float4*)d_out;

    const unsigned total = B_DIM * T_DIM * C4;   // 8,388,608
    const unsigned threads = 256;
    const unsigned blocks = total / threads;     // 32768

    ts_augment_kernel<<<blocks, threads>>>(x, noise, scale, shifts, out);
}